// round 14
// baseline (speedup 1.0000x reference)
#include <cuda_runtime.h>
#include <cuda_fp16.h>
#include <stdint.h>
#include <math.h>

#define MTOT 16384
#define DIN  1024
#define DSZ  256

// gemm1: KCH=128 halfs (256B/row), 3-stage
#define KCH1  128
#define LDR1  272
#define PLB1  (128 * LDR1)       // 34816
#define NST1  3
#define SMEM1 (NST1 * PLB1)      // 104448 -> 2 CTAs/SM
// gemm2: whole-K B resident (512B/row)
#define LDR2  528
#define SMEM2 (128 * LDR2)       // 67584 -> 2 CTAs/SM

// scan segmentation
#define NSEG 64
#define TSEG 64                  // 4096 / 64

// ---------------- scratch (__device__ globals; no allocations) ----------------
__device__ uint4  xp_g[(size_t)1024 * 64 * 32];      // x frag-packed: [band][k16][lane]
__device__ __half w1f16_g[(size_t)12 * DSZ * DIN];   // [mat*4+s][n=d][k]
__device__ __half w2f16_g[(size_t)4 * DSZ * DSZ];    // [s][n=e][k]
__device__ uint4  g1p_g[(size_t)4 * 1024 * 16 * 32]; // g1 frag-packed: [s][band][k16][lane]
__device__ __half dre_g[(size_t)4 * MTOT * DSZ];
__device__ __half dim_g[(size_t)4 * MTOT * DSZ];
__device__ float  omg_g[(size_t)4 * MTOT * DSZ];
__device__ float2 Aseg_g[1024 * 256];
__device__ float2 Hseg_g[1024 * 256];

// ---------------- helpers -------------------------------------------------------
__device__ __forceinline__ uint32_t pack_h2(float a, float b) {
    union { __half2 h; uint32_t u; } p;
    p.h = __halves2half2(__float2half_rn(a), __float2half_rn(b));
    return p.u;
}
__device__ __forceinline__ uint32_t smem_u32(const void* p) {
    uint32_t a;
    asm("{ .reg .u64 t; cvta.to.shared.u64 t, %1; cvt.u32.u64 %0, t; }" : "=r"(a) : "l"(p));
    return a;
}
__device__ __forceinline__ void cpa16(uint32_t dst, const void* src) {
    asm volatile("cp.async.cg.shared.global [%0], [%1], 16;" :: "r"(dst), "l"(src));
}
__device__ __forceinline__ void cpa_commit() {
    asm volatile("cp.async.commit_group;");
}
template<int N> __device__ __forceinline__ void cpa_wait() {
    asm volatile("cp.async.wait_group %0;" :: "n"(N));
}
__device__ __forceinline__ void ldsm4(uint32_t r[4], uint32_t addr) {
    asm volatile("ldmatrix.sync.aligned.m8n8.x4.shared.b16 {%0,%1,%2,%3}, [%4];"
        : "=r"(r[0]), "=r"(r[1]), "=r"(r[2]), "=r"(r[3]) : "r"(addr));
}
__device__ __forceinline__ void mma_f16u(float c[4], uint32_t a0, uint32_t a1, uint32_t a2, uint32_t a3,
                                         const uint32_t b[2]) {
    asm volatile("mma.sync.aligned.m16n8k16.row.col.f32.f16.f16.f32 "
        "{%0,%1,%2,%3}, {%4,%5,%6,%7}, {%8,%9}, {%0,%1,%2,%3};"
        : "+f"(c[0]), "+f"(c[1]), "+f"(c[2]), "+f"(c[3])
        : "r"(a0), "r"(a1), "r"(a2), "r"(a3), "r"(b[0]), "r"(b[1]));
}

// ---------------- GEMM 1: x @ {Wg1,Wdr,Wdi}; A reg-pipelined, B smem ------------
__global__ __launch_bounds__(256, 2) void gemm1_k(
    const float* __restrict__ bg1, const float* __restrict__ bdr, const float* __restrict__ bdi)
{
    extern __shared__ char sm[];
    uint32_t s0 = smem_u32(sm);
    const int tid = threadIdx.x;

    const int mbase = blockIdx.x * 128;
    const int nb = blockIdx.y;                 // 0..23
    const int mat = nb >> 3;
    const int s = (nb >> 1) & 3;
    const int dbase = (nb & 1) * 128;

    const int lane = tid & 31, warp = tid >> 5;
    const int wm = warp & 3, wn = warp >> 2;
    const int band0 = (mbase >> 4) + wm * 2;

    const uint4* pA0 = xp_g + ((size_t)band0 * 64) * 32 + lane;
    const uint4* pA1 = xp_g + ((size_t)(band0 + 1) * 64) * 32 + lane;
    const __half* gB = w1f16_g + ((size_t)(mat * 4 + s) * DSZ + dbase) * DIN;
    const uint32_t bBase = (uint32_t)(wn * 64 + (lane & 7) + ((lane & 16) >> 1)) * LDR1
                         + ((lane >> 3) & 1) * 16;

    auto issueB = [&](int st, int k0) {
        uint32_t base = s0 + st * PLB1;
#pragma unroll
        for (int it = 0; it < 8; it++) {
            int q = tid + it * 256;
            int r = q >> 4, c = q & 15;
            cpa16(base + r * LDR1 + c * 16, gB + (size_t)r * DIN + k0 + c * 8);
        }
        cpa_commit();
    };

    float acc[2][8][4];
#pragma unroll
    for (int i = 0; i < 2; i++)
#pragma unroll
        for (int j = 0; j < 8; j++)
#pragma unroll
            for (int k = 0; k < 4; k++) acc[i][j][k] = 0.f;

    constexpr int NCH = DIN / KCH1;    // 8
    issueB(0, 0);
    issueB(1, KCH1);

    // distance-2 A fragment register pipeline over flat k16 stream
    uint4 f0a = pA0[0],  f0b = pA1[0];
    uint4 f1a = pA0[32], f1b = pA1[32];

    int st = 0;
    for (int ch = 0; ch < NCH; ch++) {
        if (ch >= NCH - 1) cpa_wait<0>(); else cpa_wait<1>();
        __syncthreads();
        if (ch + 2 < NCH) {
            int st2 = st + 2; if (st2 >= 3) st2 -= 3;
            issueB(st2, (ch + 2) * KCH1);
        }
        const uint32_t sb = s0 + st * PLB1;
#pragma unroll
        for (int ks = 0; ks < 8; ks++) {
            const int k16 = ch * 8 + ks;
            const uint4 a0 = f0a, a1 = f0b;
            f0a = f1a; f0b = f1b;
            if (k16 + 2 < 64) {
                f1a = pA0[(size_t)(k16 + 2) * 32];
                f1b = pA1[(size_t)(k16 + 2) * 32];
            }
            uint32_t bb[4][4];
#pragma unroll
            for (int nf4 = 0; nf4 < 4; nf4++)
                ldsm4(bb[nf4], sb + bBase + nf4 * (16 * LDR1) + ks * 32);
#pragma unroll
            for (int nf = 0; nf < 8; nf++) {
                const uint32_t* bp = &bb[nf >> 1][(nf & 1) * 2];
                mma_f16u(acc[0][nf], a0.x, a0.y, a0.z, a0.w, bp);
                mma_f16u(acc[1][nf], a1.x, a1.y, a1.z, a1.w, bp);
            }
        }
        if (++st >= 3) st = 0;
    }

    const int c0 = wn * 64 + (lane & 3) * 2;
    const float* bias = (mat == 0 ? bg1 : (mat == 1 ? bdr : bdi)) + s * DSZ + dbase;

    if (mat == 0) {
        uint4* gp = g1p_g + ((size_t)s * 1024 * 16) * 32;
#pragma unroll
        for (int mi = 0; mi < 2; mi++) {
            const int band = band0 + mi;
#pragma unroll
            for (int p = 0; p < 4; p++) {
                const int nf = 2 * p;
                const int col = c0 + nf * 8;
                float b0 = bias[col],      b1 = bias[col + 1];
                float b2 = bias[col + 8],  b3 = bias[col + 9];
                uint4 w;
                w.x = pack_h2(fmaxf(acc[mi][nf][0] + b0, 0.f),
                              fmaxf(acc[mi][nf][1] + b1, 0.f));
                w.y = pack_h2(fmaxf(acc[mi][nf][2] + b0, 0.f),
                              fmaxf(acc[mi][nf][3] + b1, 0.f));
                w.z = pack_h2(fmaxf(acc[mi][nf + 1][0] + b2, 0.f),
                              fmaxf(acc[mi][nf + 1][1] + b3, 0.f));
                w.w = pack_h2(fmaxf(acc[mi][nf + 1][2] + b2, 0.f),
                              fmaxf(acc[mi][nf + 1][3] + b3, 0.f));
                const int k16 = (dbase + wn * 64 + nf * 8) >> 4;
                gp[((size_t)band * 16 + k16) * 32 + lane] = w;
            }
        }
    } else {
        const int r0 = mbase + wm * 32 + (lane >> 2);
        __half* op = (mat == 1 ? dre_g : dim_g) + (size_t)s * MTOT * DSZ;
#pragma unroll
        for (int mi = 0; mi < 2; mi++)
#pragma unroll
            for (int nf = 0; nf < 8; nf++) {
                int col = c0 + nf * 8;
                float b0 = bias[col], b1 = bias[col + 1];
#pragma unroll
                for (int hh = 0; hh < 2; hh++) {
                    int r = r0 + mi * 16 + hh * 8;
                    union { __half2 h; uint32_t u; } pk;
                    pk.u = pack_h2(acc[mi][nf][hh * 2 + 0] + b0,
                                   acc[mi][nf][hh * 2 + 1] + b1);
                    *(__half2*)(op + (size_t)r * DSZ + dbase + col) = pk.h;
                }
            }
    }
}

// ---------------- GEMM 2: B resident, 4 m-tiles/CTA, A reg-pipelined ------------
__global__ __launch_bounds__(256, 2) void gemm2_k(const float* __restrict__ bg2)
{
    extern __shared__ char sm[];
    uint32_t s0 = smem_u32(sm);
    const int tid = threadIdx.x;

    const int mgrp = blockIdx.x;               // 0..31 -> 4 m-tiles each
    const int s = blockIdx.y >> 1;
    const int dbase = (blockIdx.y & 1) * 128;

    const int lane = tid & 31, warp = tid >> 5;
    const int wm = warp & 3, wn = warp >> 2;

    const __half* gB = w2f16_g + ((size_t)s * DSZ + dbase) * DSZ;

#pragma unroll
    for (int it = 0; it < 16; it++) {
        int q = tid + it * 256;
        int r = q >> 5, c = q & 31;
        cpa16(s0 + r * LDR2 + c * 16, gB + (size_t)r * DSZ + c * 8);
    }
    cpa_commit();

    const uint32_t bBase = (uint32_t)(wn * 64 + (lane & 7) + ((lane & 16) >> 1)) * LDR2
                         + ((lane >> 3) & 1) * 16;
    const int c0 = wn * 64 + (lane & 3) * 2;
    const float* bias = bg2 + s * DSZ + dbase;
    float* opb = omg_g + (size_t)s * MTOT * DSZ;

    cpa_wait<0>();
    __syncthreads();

    for (int mt = 0; mt < 4; mt++) {
        const int mbase = (mgrp * 4 + mt) * 128;
        const int band0 = (mbase >> 4) + wm * 2;
        const uint4* pA0 = g1p_g + ((size_t)(s * 1024 + band0) * 16) * 32 + lane;
        const uint4* pA1 = g1p_g + ((size_t)(s * 1024 + band0 + 1) * 16) * 32 + lane;

        float acc[2][8][4];
#pragma unroll
        for (int i = 0; i < 2; i++)
#pragma unroll
            for (int j = 0; j < 8; j++)
#pragma unroll
                for (int k = 0; k < 4; k++) acc[i][j][k] = 0.f;

        uint4 f0a = pA0[0],  f0b = pA1[0];
        uint4 f1a = pA0[32], f1b = pA1[32];

#pragma unroll
        for (int k16 = 0; k16 < 16; k16++) {
            const uint4 a0 = f0a, a1 = f0b;
            f0a = f1a; f0b = f1b;
            if (k16 + 2 < 16) {
                f1a = pA0[(size_t)(k16 + 2) * 32];
                f1b = pA1[(size_t)(k16 + 2) * 32];
            }
            uint32_t bb[4][4];
#pragma unroll
            for (int nf4 = 0; nf4 < 4; nf4++)
                ldsm4(bb[nf4], s0 + bBase + nf4 * (16 * LDR2) + k16 * 32);
#pragma unroll
            for (int nf = 0; nf < 8; nf++) {
                const uint32_t* bp = &bb[nf >> 1][(nf & 1) * 2];
                mma_f16u(acc[0][nf], a0.x, a0.y, a0.z, a0.w, bp);
                mma_f16u(acc[1][nf], a1.x, a1.y, a1.z, a1.w, bp);
            }
        }

        const int r0 = mbase + wm * 32 + (lane >> 2);
#pragma unroll
        for (int mi = 0; mi < 2; mi++)
#pragma unroll
            for (int nf = 0; nf < 8; nf++) {
                int col = c0 + nf * 8;
                float b0 = bias[col], b1 = bias[col + 1];
#pragma unroll
                for (int hh = 0; hh < 2; hh++) {
                    int r = r0 + mi * 16 + hh * 8;
                    float2 v;
                    v.x = __fdividef(1.0f, 1.0f + __expf(acc[mi][nf][hh * 2 + 0] + b0));
                    v.y = __fdividef(1.0f, 1.0f + __expf(acc[mi][nf][hh * 2 + 1] + b1));
                    *(float2*)(opb + (size_t)r * DSZ + dbase + col) = v;
                }
            }
    }
}

// ---------------- conversion kernels -------------------------------------------
__global__ __launch_bounds__(256) void conv_x_k(const float* __restrict__ x) {
    const size_t idx = (size_t)blockIdx.x * 256 + threadIdx.x;
    const int lane = idx & 31;
    const int k16  = ((int)(idx >> 5)) & 63;
    const int band = (int)(idx >> 11);
    const int g = lane >> 2, t = lane & 3;
    const size_t r0 = (size_t)(band * 16 + g) * DIN;
    const size_t r8 = r0 + 8 * DIN;
    const int col = k16 * 16 + 2 * t;
    float2 v00 = *(const float2*)(x + r0 + col);
    float2 v10 = *(const float2*)(x + r8 + col);
    float2 v01 = *(const float2*)(x + r0 + col + 8);
    float2 v11 = *(const float2*)(x + r8 + col + 8);
    uint4 w;
    w.x = pack_h2(v00.x, v00.y);
    w.y = pack_h2(v10.x, v10.y);
    w.z = pack_h2(v01.x, v01.y);
    w.w = pack_h2(v11.x, v11.y);
    xp_g[idx] = w;
}

__global__ void conv_w_all_k(const float* __restrict__ Wg1,
                             const float* __restrict__ Wdr,
                             const float* __restrict__ Wdi,
                             const float* __restrict__ Wg2) {
    __shared__ float t[32][33];
    int z = blockIdx.z;
    const int kdim = (z < 12) ? DIN : DSZ;
    if (blockIdx.x * 32 >= kdim) return;
    const float* base = (z < 4 ? Wg1 : (z < 8 ? Wdr : (z < 12 ? Wdi : Wg2)));
    const float* sp = base + (size_t)(z & 3) * kdim * DSZ;
    int tx = threadIdx.x, ty = threadIdx.y;
    int k0 = blockIdx.x * 32, d0 = blockIdx.y * 32;
#pragma unroll
    for (int i = 0; i < 4; i++)
        t[ty + i * 8][tx] = sp[(size_t)(k0 + ty + i * 8) * DSZ + d0 + tx];
    __syncthreads();
    __half* oh = (z < 12) ? (w1f16_g + (size_t)z * DSZ * DIN)
                          : (w2f16_g + (size_t)(z - 12) * DSZ * DSZ);
#pragma unroll
    for (int i = 0; i < 4; i++) {
        int n = d0 + ty + i * 8, k = k0 + tx;
        oh[(size_t)n * kdim + k] = __float2half_rn(t[tx][ty + i * 8]);
    }
}

// ---------------- segmented scan (2 phases, 64 segments) ------------------------
struct ScanConsts { float abr[4], abi[4], bsc[4]; };

__global__ __launch_bounds__(256) void scan_p1(ScanConsts c) {
    const int idx = blockIdx.x;                // b*256 + s*64 + seg
    const int seg = idx & (NSEG - 1), s = (idx >> 6) & 3, b = idx >> 8;
    const int d = threadIdx.x;
    const float abr = c.abr[s], abi = c.abi[s], bs = c.bsc[s];
    const size_t base = ((size_t)s * MTOT + (size_t)b * 4096 + seg * TSEG) * DSZ + d;
    float Ar = 1.f, Ai = 0.f, Hr = 0.f, Hi = 0.f;
#pragma unroll 4
    for (int t = 0; t < TSEG; t++) {
        size_t off = base + (size_t)t * DSZ;
        float w  = omg_g[off];
        float xr = __half2float(dre_g[off]);
        float xi = __half2float(dim_g[off]);
        float ar = w * abr, ai = w * abi, wb = w * bs;
        float br = wb * xr, bi = wb * xi;
        float nHr = fmaf(ar, Hr, fmaf(-ai, Hi, br));
        float nHi = fmaf(ar, Hi, fmaf( ai, Hr, bi));
        float nAr = fmaf(ar, Ar, -ai * Ai);
        float nAi = fmaf(ar, Ai,  ai * Ar);
        Hr = nHr; Hi = nHi; Ar = nAr; Ai = nAi;
    }
    Aseg_g[idx * 256 + d] = make_float2(Ar, Ai);
    Hseg_g[idx * 256 + d] = make_float2(Hr, Hi);
}

__global__ __launch_bounds__(256) void scan_p3(float* __restrict__ out, ScanConsts c) {
    const int idx = blockIdx.x;
    const int seg = idx & (NSEG - 1), s = (idx >> 6) & 3, b = idx >> 8;
    const int d = threadIdx.x;
    const float abr = c.abr[s], abi = c.abi[s], bs = c.bsc[s];
    const size_t base = ((size_t)s * MTOT + (size_t)b * 4096 + seg * TSEG) * DSZ + d;

    float hr = 0.f, hi = 0.f;
    const int rowbase = idx - seg;
    for (int g = 0; g < seg; g++) {
        float2 A = Aseg_g[(rowbase + g) * 256 + d];
        float2 H = Hseg_g[(rowbase + g) * 256 + d];
        float nhr = fmaf(A.x, hr, fmaf(-A.y, hi, H.x));
        float nhi = fmaf(A.x, hi, fmaf( A.y, hr, H.y));
        hr = nhr; hi = nhi;
    }

    float* op = out + ((size_t)b * 4096 + seg * TSEG) * 2048 + (size_t)s * 512 + d;
#pragma unroll 4
    for (int t = 0; t < TSEG; t++) {
        size_t off = base + (size_t)t * DSZ;
        float w  = omg_g[off];
        float xr = __half2float(dre_g[off]);
        float xi = __half2float(dim_g[off]);
        float ar = w * abr, ai = w * abi, wb = w * bs;
        float br = wb * xr, bi = wb * xi;
        float nhr = fmaf(ar, hr, fmaf(-ai, hi, br));
        float nhi = fmaf(ar, hi, fmaf( ai, hr, bi));
        hr = nhr; hi = nhi;
        op[(size_t)t * 2048]       = hr;
        op[(size_t)t * 2048 + 256] = hi;
    }
}

// ---------------- host ----------------------------------------------------------
extern "C" void kernel_launch(void* const* d_in, const int* in_sizes, int n_in,
                              void* d_out, int out_size)
{
    const float* x   = (const float*)d_in[0];
    const float* Wg1 = (const float*)d_in[1];
    const float* bg1 = (const float*)d_in[2];
    const float* Wg2 = (const float*)d_in[3];
    const float* bg2 = (const float*)d_in[4];
    const float* Wdr = (const float*)d_in[5];
    const float* bdr = (const float*)d_in[6];
    const float* Wdi = (const float*)d_in[7];
    const float* bdi = (const float*)d_in[8];
    float* out = (float*)d_out;

    cudaFuncSetAttribute(gemm1_k, cudaFuncAttributeMaxDynamicSharedMemorySize, SMEM1);
    cudaFuncSetAttribute(gemm2_k, cudaFuncAttributeMaxDynamicSharedMemorySize, SMEM2);

    conv_x_k<<<8192, 256>>>(x);
    dim3 tb(32, 8);
    conv_w_all_k<<<dim3(32, 8, 16), tb>>>(Wg1, Wdr, Wdi, Wg2);

    gemm1_k<<<dim3(MTOT / 128, 24), 256, SMEM1>>>(bg1, bdr, bdi);
    gemm2_k<<<dim3(32, 8), 256, SMEM2>>>(bg2);

    ScanConsts c;
    const double r [4] = {1.0, 0.999, 0.9495, 0.9};
    const double th[4] = {0.0, 0.01,  0.505,  1.0};
    for (int s = 0; s < 4; s++) {
        c.abr[s] = (float)(r[s] * cos(th[s]));
        c.abi[s] = (float)(r[s] * sin(th[s]));
        c.bsc[s] = (float)((r[s] >= 1.0) ? (1.0 / 16.0) : (1.0 - r[s]));
    }
    scan_p1<<<1024, 256>>>(c);
    scan_p3<<<1024, 256>>>(out, c);
}

// round 15
// speedup vs baseline: 1.0640x; 1.0640x over previous
#include <cuda_runtime.h>
#include <cuda_fp16.h>
#include <stdint.h>
#include <math.h>

#define MTOT 16384
#define DIN  1024
#define DSZ  256

// gemm1: KCH=128 halfs (256B/row), 3-stage
#define KCH1  128
#define LDR1  272
#define PLB1  (128 * LDR1)       // 34816
#define NST1  3
#define SMEM1 (NST1 * PLB1)      // 104448 -> 2 CTAs/SM
// gemm2: whole-K B resident (512B/row)
#define LDR2  528
#define SMEM2 (128 * LDR2)       // 67584 -> 2 CTAs/SM

// scan segmentation (R13 geometry)
#define NSEG 32
#define TSEG 128                 // 4096 / 32

// ---------------- scratch (__device__ globals; no allocations) ----------------
__device__ uint4  xp_g[(size_t)1024 * 64 * 32];      // x frag-packed: [band][k16][lane]
__device__ __half w1f16_g[(size_t)12 * DSZ * DIN];   // [mat*4+s][n=d][k]
__device__ __half w2f16_g[(size_t)4 * DSZ * DSZ];    // [s][n=e][k]
__device__ uint4  g1p_g[(size_t)4 * 1024 * 16 * 32]; // g1 frag-packed: [s][band][k16][lane]
__device__ __half dre_g[(size_t)4 * MTOT * DSZ];
__device__ __half dim_g[(size_t)4 * MTOT * DSZ];
__device__ float  omg_g[(size_t)4 * MTOT * DSZ];
__device__ float2 Aseg_g[512 * 256];
__device__ float2 Hseg_g[512 * 256];

// ---------------- helpers -------------------------------------------------------
__device__ __forceinline__ uint32_t pack_h2(float a, float b) {
    union { __half2 h; uint32_t u; } p;
    p.h = __halves2half2(__float2half_rn(a), __float2half_rn(b));
    return p.u;
}
__device__ __forceinline__ uint32_t smem_u32(const void* p) {
    uint32_t a;
    asm("{ .reg .u64 t; cvta.to.shared.u64 t, %1; cvt.u32.u64 %0, t; }" : "=r"(a) : "l"(p));
    return a;
}
__device__ __forceinline__ void cpa16(uint32_t dst, const void* src) {
    asm volatile("cp.async.cg.shared.global [%0], [%1], 16;" :: "r"(dst), "l"(src));
}
__device__ __forceinline__ void cpa_commit() {
    asm volatile("cp.async.commit_group;");
}
template<int N> __device__ __forceinline__ void cpa_wait() {
    asm volatile("cp.async.wait_group %0;" :: "n"(N));
}
__device__ __forceinline__ void ldsm4(uint32_t r[4], uint32_t addr) {
    asm volatile("ldmatrix.sync.aligned.m8n8.x4.shared.b16 {%0,%1,%2,%3}, [%4];"
        : "=r"(r[0]), "=r"(r[1]), "=r"(r[2]), "=r"(r[3]) : "r"(addr));
}
__device__ __forceinline__ void mma_f16u(float c[4], uint32_t a0, uint32_t a1, uint32_t a2, uint32_t a3,
                                         const uint32_t b[2]) {
    asm volatile("mma.sync.aligned.m16n8k16.row.col.f32.f16.f16.f32 "
        "{%0,%1,%2,%3}, {%4,%5,%6,%7}, {%8,%9}, {%0,%1,%2,%3};"
        : "+f"(c[0]), "+f"(c[1]), "+f"(c[2]), "+f"(c[3])
        : "r"(a0), "r"(a1), "r"(a2), "r"(a3), "r"(b[0]), "r"(b[1]));
}

// ---------------- GEMM 1 (R13 version): A frag-direct + ks0 prefetch ------------
__global__ __launch_bounds__(256, 2) void gemm1_k(
    const float* __restrict__ bg1, const float* __restrict__ bdr, const float* __restrict__ bdi)
{
    extern __shared__ char sm[];
    uint32_t s0 = smem_u32(sm);
    const int tid = threadIdx.x;

    const int mbase = blockIdx.x * 128;
    const int nb = blockIdx.y;                 // 0..23
    const int mat = nb >> 3;
    const int s = (nb >> 1) & 3;
    const int dbase = (nb & 1) * 128;

    const int lane = tid & 31, warp = tid >> 5;
    const int wm = warp & 3, wn = warp >> 2;
    const int band0 = (mbase >> 4) + wm * 2;

    const uint4* pA0 = xp_g + ((size_t)band0 * 64) * 32 + lane;
    const uint4* pA1 = xp_g + ((size_t)(band0 + 1) * 64) * 32 + lane;
    const __half* gB = w1f16_g + ((size_t)(mat * 4 + s) * DSZ + dbase) * DIN;
    const uint32_t bBase = (uint32_t)(wn * 64 + (lane & 7) + ((lane & 16) >> 1)) * LDR1
                         + ((lane >> 3) & 1) * 16;

    auto issueB = [&](int st, int k0) {
        uint32_t base = s0 + st * PLB1;
#pragma unroll
        for (int it = 0; it < 8; it++) {
            int q = tid + it * 256;
            int r = q >> 4, c = q & 15;
            cpa16(base + r * LDR1 + c * 16, gB + (size_t)r * DIN + k0 + c * 8);
        }
        cpa_commit();
    };

    float acc[2][8][4];
#pragma unroll
    for (int i = 0; i < 2; i++)
#pragma unroll
        for (int j = 0; j < 8; j++)
#pragma unroll
            for (int k = 0; k < 4; k++) acc[i][j][k] = 0.f;

    constexpr int NCH = DIN / KCH1;    // 8
    issueB(0, 0);
    issueB(1, KCH1);

    uint4 a0n = pA0[0];
    uint4 a1n = pA1[0];

    int st = 0;
    for (int ch = 0; ch < NCH; ch++) {
        if (ch >= NCH - 1) cpa_wait<0>(); else cpa_wait<1>();
        __syncthreads();
        if (ch + 2 < NCH) {
            int st2 = st + 2; if (st2 >= 3) st2 -= 3;
            issueB(st2, (ch + 2) * KCH1);
        }
        const uint4 a0c = a0n, a1c = a1n;
        if (ch + 1 < NCH) {
            a0n = pA0[(size_t)(ch + 1) * 8 * 32];
            a1n = pA1[(size_t)(ch + 1) * 8 * 32];
        }
        const uint32_t sb = s0 + st * PLB1;
#pragma unroll
        for (int ks = 0; ks < 8; ks++) {
            const int k16 = ch * 8 + ks;
            uint4 a0 = (ks == 0) ? a0c : pA0[(size_t)k16 * 32];
            uint4 a1 = (ks == 0) ? a1c : pA1[(size_t)k16 * 32];
            uint32_t bb[4][4];
#pragma unroll
            for (int nf4 = 0; nf4 < 4; nf4++)
                ldsm4(bb[nf4], sb + bBase + nf4 * (16 * LDR1) + ks * 32);
#pragma unroll
            for (int nf = 0; nf < 8; nf++) {
                const uint32_t* bp = &bb[nf >> 1][(nf & 1) * 2];
                mma_f16u(acc[0][nf], a0.x, a0.y, a0.z, a0.w, bp);
                mma_f16u(acc[1][nf], a1.x, a1.y, a1.z, a1.w, bp);
            }
        }
        if (++st >= 3) st = 0;
    }

    const int c0 = wn * 64 + (lane & 3) * 2;
    const float* bias = (mat == 0 ? bg1 : (mat == 1 ? bdr : bdi)) + s * DSZ + dbase;

    if (mat == 0) {
        uint4* gp = g1p_g + ((size_t)s * 1024 * 16) * 32;
#pragma unroll
        for (int mi = 0; mi < 2; mi++) {
            const int band = band0 + mi;
#pragma unroll
            for (int p = 0; p < 4; p++) {
                const int nf = 2 * p;
                const int col = c0 + nf * 8;
                float b0 = bias[col],      b1 = bias[col + 1];
                float b2 = bias[col + 8],  b3 = bias[col + 9];
                uint4 w;
                w.x = pack_h2(fmaxf(acc[mi][nf][0] + b0, 0.f),
                              fmaxf(acc[mi][nf][1] + b1, 0.f));
                w.y = pack_h2(fmaxf(acc[mi][nf][2] + b0, 0.f),
                              fmaxf(acc[mi][nf][3] + b1, 0.f));
                w.z = pack_h2(fmaxf(acc[mi][nf + 1][0] + b2, 0.f),
                              fmaxf(acc[mi][nf + 1][1] + b3, 0.f));
                w.w = pack_h2(fmaxf(acc[mi][nf + 1][2] + b2, 0.f),
                              fmaxf(acc[mi][nf + 1][3] + b3, 0.f));
                const int k16 = (dbase + wn * 64 + nf * 8) >> 4;
                gp[((size_t)band * 16 + k16) * 32 + lane] = w;
            }
        }
    } else {
        const int r0 = mbase + wm * 32 + (lane >> 2);
        __half* op = (mat == 1 ? dre_g : dim_g) + (size_t)s * MTOT * DSZ;
#pragma unroll
        for (int mi = 0; mi < 2; mi++)
#pragma unroll
            for (int nf = 0; nf < 8; nf++) {
                int col = c0 + nf * 8;
                float b0 = bias[col], b1 = bias[col + 1];
#pragma unroll
                for (int hh = 0; hh < 2; hh++) {
                    int r = r0 + mi * 16 + hh * 8;
                    union { __half2 h; uint32_t u; } pk;
                    pk.u = pack_h2(acc[mi][nf][hh * 2 + 0] + b0,
                                   acc[mi][nf][hh * 2 + 1] + b1);
                    *(__half2*)(op + (size_t)r * DSZ + dbase + col) = pk.h;
                }
            }
    }
}

// ---------------- GEMM 2 (R14 version): B resident, reg-pipelined A, fast epi ---
__global__ __launch_bounds__(256, 2) void gemm2_k(const float* __restrict__ bg2)
{
    extern __shared__ char sm[];
    uint32_t s0 = smem_u32(sm);
    const int tid = threadIdx.x;

    const int mgrp = blockIdx.x;               // 0..31 -> 4 m-tiles each
    const int s = blockIdx.y >> 1;
    const int dbase = (blockIdx.y & 1) * 128;

    const int lane = tid & 31, warp = tid >> 5;
    const int wm = warp & 3, wn = warp >> 2;

    const __half* gB = w2f16_g + ((size_t)s * DSZ + dbase) * DSZ;

#pragma unroll
    for (int it = 0; it < 16; it++) {
        int q = tid + it * 256;
        int r = q >> 5, c = q & 31;
        cpa16(s0 + r * LDR2 + c * 16, gB + (size_t)r * DSZ + c * 8);
    }
    cpa_commit();

    const uint32_t bBase = (uint32_t)(wn * 64 + (lane & 7) + ((lane & 16) >> 1)) * LDR2
                         + ((lane >> 3) & 1) * 16;
    const int c0 = wn * 64 + (lane & 3) * 2;
    const float* bias = bg2 + s * DSZ + dbase;
    float* opb = omg_g + (size_t)s * MTOT * DSZ;

    cpa_wait<0>();
    __syncthreads();

    for (int mt = 0; mt < 4; mt++) {
        const int mbase = (mgrp * 4 + mt) * 128;
        const int band0 = (mbase >> 4) + wm * 2;
        const uint4* pA0 = g1p_g + ((size_t)(s * 1024 + band0) * 16) * 32 + lane;
        const uint4* pA1 = g1p_g + ((size_t)(s * 1024 + band0 + 1) * 16) * 32 + lane;

        float acc[2][8][4];
#pragma unroll
        for (int i = 0; i < 2; i++)
#pragma unroll
            for (int j = 0; j < 8; j++)
#pragma unroll
                for (int k = 0; k < 4; k++) acc[i][j][k] = 0.f;

        uint4 f0a = pA0[0],  f0b = pA1[0];
        uint4 f1a = pA0[32], f1b = pA1[32];

#pragma unroll
        for (int k16 = 0; k16 < 16; k16++) {
            const uint4 a0 = f0a, a1 = f0b;
            f0a = f1a; f0b = f1b;
            if (k16 + 2 < 16) {
                f1a = pA0[(size_t)(k16 + 2) * 32];
                f1b = pA1[(size_t)(k16 + 2) * 32];
            }
            uint32_t bb[4][4];
#pragma unroll
            for (int nf4 = 0; nf4 < 4; nf4++)
                ldsm4(bb[nf4], s0 + bBase + nf4 * (16 * LDR2) + k16 * 32);
#pragma unroll
            for (int nf = 0; nf < 8; nf++) {
                const uint32_t* bp = &bb[nf >> 1][(nf & 1) * 2];
                mma_f16u(acc[0][nf], a0.x, a0.y, a0.z, a0.w, bp);
                mma_f16u(acc[1][nf], a1.x, a1.y, a1.z, a1.w, bp);
            }
        }

        const int r0 = mbase + wm * 32 + (lane >> 2);
#pragma unroll
        for (int mi = 0; mi < 2; mi++)
#pragma unroll
            for (int nf = 0; nf < 8; nf++) {
                int col = c0 + nf * 8;
                float b0 = bias[col], b1 = bias[col + 1];
#pragma unroll
                for (int hh = 0; hh < 2; hh++) {
                    int r = r0 + mi * 16 + hh * 8;
                    float2 v;
                    v.x = __fdividef(1.0f, 1.0f + __expf(acc[mi][nf][hh * 2 + 0] + b0));
                    v.y = __fdividef(1.0f, 1.0f + __expf(acc[mi][nf][hh * 2 + 1] + b1));
                    *(float2*)(opb + (size_t)r * DSZ + dbase + col) = v;
                }
            }
    }
}

// ---------------- conversion kernels -------------------------------------------
__global__ __launch_bounds__(256) void conv_x_k(const float* __restrict__ x) {
    const size_t idx = (size_t)blockIdx.x * 256 + threadIdx.x;
    const int lane = idx & 31;
    const int k16  = ((int)(idx >> 5)) & 63;
    const int band = (int)(idx >> 11);
    const int g = lane >> 2, t = lane & 3;
    const size_t r0 = (size_t)(band * 16 + g) * DIN;
    const size_t r8 = r0 + 8 * DIN;
    const int col = k16 * 16 + 2 * t;
    float2 v00 = *(const float2*)(x + r0 + col);
    float2 v10 = *(const float2*)(x + r8 + col);
    float2 v01 = *(const float2*)(x + r0 + col + 8);
    float2 v11 = *(const float2*)(x + r8 + col + 8);
    uint4 w;
    w.x = pack_h2(v00.x, v00.y);
    w.y = pack_h2(v10.x, v10.y);
    w.z = pack_h2(v01.x, v01.y);
    w.w = pack_h2(v11.x, v11.y);
    xp_g[idx] = w;
}

__global__ void conv_w_all_k(const float* __restrict__ Wg1,
                             const float* __restrict__ Wdr,
                             const float* __restrict__ Wdi,
                             const float* __restrict__ Wg2) {
    __shared__ float t[32][33];
    int z = blockIdx.z;
    const int kdim = (z < 12) ? DIN : DSZ;
    if (blockIdx.x * 32 >= kdim) return;
    const float* base = (z < 4 ? Wg1 : (z < 8 ? Wdr : (z < 12 ? Wdi : Wg2)));
    const float* sp = base + (size_t)(z & 3) * kdim * DSZ;
    int tx = threadIdx.x, ty = threadIdx.y;
    int k0 = blockIdx.x * 32, d0 = blockIdx.y * 32;
#pragma unroll
    for (int i = 0; i < 4; i++)
        t[ty + i * 8][tx] = sp[(size_t)(k0 + ty + i * 8) * DSZ + d0 + tx];
    __syncthreads();
    __half* oh = (z < 12) ? (w1f16_g + (size_t)z * DSZ * DIN)
                          : (w2f16_g + (size_t)(z - 12) * DSZ * DSZ);
#pragma unroll
    for (int i = 0; i < 4; i++) {
        int n = d0 + ty + i * 8, k = k0 + tx;
        oh[(size_t)n * kdim + k] = __float2half_rn(t[tx][ty + i * 8]);
    }
}

// ---------------- segmented scan (2 phases, 32 segments — R13 geometry) ---------
struct ScanConsts { float abr[4], abi[4], bsc[4]; };

__global__ __launch_bounds__(256) void scan_p1(ScanConsts c) {
    const int idx = blockIdx.x;                // b*128 + s*32 + seg
    const int seg = idx & (NSEG - 1), s = (idx >> 5) & 3, b = idx >> 7;
    const int d = threadIdx.x;
    const float abr = c.abr[s], abi = c.abi[s], bs = c.bsc[s];
    const size_t base = ((size_t)s * MTOT + (size_t)b * 4096 + seg * TSEG) * DSZ + d;
    float Ar = 1.f, Ai = 0.f, Hr = 0.f, Hi = 0.f;
#pragma unroll 4
    for (int t = 0; t < TSEG; t++) {
        size_t off = base + (size_t)t * DSZ;
        float w  = omg_g[off];
        float xr = __half2float(dre_g[off]);
        float xi = __half2float(dim_g[off]);
        float ar = w * abr, ai = w * abi, wb = w * bs;
        float br = wb * xr, bi = wb * xi;
        float nHr = fmaf(ar, Hr, fmaf(-ai, Hi, br));
        float nHi = fmaf(ar, Hi, fmaf( ai, Hr, bi));
        float nAr = fmaf(ar, Ar, -ai * Ai);
        float nAi = fmaf(ar, Ai,  ai * Ar);
        Hr = nHr; Hi = nHi; Ar = nAr; Ai = nAi;
    }
    Aseg_g[idx * 256 + d] = make_float2(Ar, Ai);
    Hseg_g[idx * 256 + d] = make_float2(Hr, Hi);
}

__global__ __launch_bounds__(256) void scan_p3(float* __restrict__ out, ScanConsts c) {
    const int idx = blockIdx.x;
    const int seg = idx & (NSEG - 1), s = (idx >> 5) & 3, b = idx >> 7;
    const int d = threadIdx.x;
    const float abr = c.abr[s], abi = c.abi[s], bs = c.bsc[s];
    const size_t base = ((size_t)s * MTOT + (size_t)b * 4096 + seg * TSEG) * DSZ + d;

    float hr = 0.f, hi = 0.f;
    const int rowbase = idx - seg;
    for (int g = 0; g < seg; g++) {
        float2 A = Aseg_g[(rowbase + g) * 256 + d];
        float2 H = Hseg_g[(rowbase + g) * 256 + d];
        float nhr = fmaf(A.x, hr, fmaf(-A.y, hi, H.x));
        float nhi = fmaf(A.x, hi, fmaf( A.y, hr, H.y));
        hr = nhr; hi = nhi;
    }

    float* op = out + ((size_t)b * 4096 + seg * TSEG) * 2048 + (size_t)s * 512 + d;
#pragma unroll 4
    for (int t = 0; t < TSEG; t++) {
        size_t off = base + (size_t)t * DSZ;
        float w  = omg_g[off];
        float xr = __half2float(dre_g[off]);
        float xi = __half2float(dim_g[off]);
        float ar = w * abr, ai = w * abi, wb = w * bs;
        float br = wb * xr, bi = wb * xi;
        float nhr = fmaf(ar, hr, fmaf(-ai, hi, br));
        float nhi = fmaf(ar, hi, fmaf( ai, hr, bi));
        hr = nhr; hi = nhi;
        op[(size_t)t * 2048]       = hr;
        op[(size_t)t * 2048 + 256] = hi;
    }
}

// ---------------- host ----------------------------------------------------------
extern "C" void kernel_launch(void* const* d_in, const int* in_sizes, int n_in,
                              void* d_out, int out_size)
{
    const float* x   = (const float*)d_in[0];
    const float* Wg1 = (const float*)d_in[1];
    const float* bg1 = (const float*)d_in[2];
    const float* Wg2 = (const float*)d_in[3];
    const float* bg2 = (const float*)d_in[4];
    const float* Wdr = (const float*)d_in[5];
    const float* bdr = (const float*)d_in[6];
    const float* Wdi = (const float*)d_in[7];
    const float* bdi = (const float*)d_in[8];
    float* out = (float*)d_out;

    cudaFuncSetAttribute(gemm1_k, cudaFuncAttributeMaxDynamicSharedMemorySize, SMEM1);
    cudaFuncSetAttribute(gemm2_k, cudaFuncAttributeMaxDynamicSharedMemorySize, SMEM2);

    conv_x_k<<<8192, 256>>>(x);
    dim3 tb(32, 8);
    conv_w_all_k<<<dim3(32, 8, 16), tb>>>(Wg1, Wdr, Wdi, Wg2);

    gemm1_k<<<dim3(MTOT / 128, 24), 256, SMEM1>>>(bg1, bdr, bdi);
    gemm2_k<<<dim3(32, 8), 256, SMEM2>>>(bg2);

    ScanConsts c;
    const double r [4] = {1.0, 0.999, 0.9495, 0.9};
    const double th[4] = {0.0, 0.01,  0.505,  1.0};
    for (int s = 0; s < 4; s++) {
        c.abr[s] = (float)(r[s] * cos(th[s]));
        c.abi[s] = (float)(r[s] * sin(th[s]));
        c.bsc[s] = (float)((r[s] >= 1.0) ? (1.0 / 16.0) : (1.0 - r[s]));
    }
    scan_p1<<<512, 256>>>(c);
    scan_p3<<<512, 256>>>(out, c);
}

// round 16
// speedup vs baseline: 1.0748x; 1.0102x over previous
#include <cuda_runtime.h>
#include <cuda_fp16.h>
#include <stdint.h>
#include <math.h>

#define MTOT 16384
#define DIN  1024
#define DSZ  256

// gemm1: KCH=128 halfs (256B/row), 3-stage
#define KCH1  128
#define LDR1  272
#define PLB1  (128 * LDR1)       // 34816
#define NST1  3
#define SMEM1 (NST1 * PLB1)      // 104448 -> 2 CTAs/SM
// gemm2: whole-K B resident (512B/row)
#define LDR2  528
#define SMEM2 (128 * LDR2)       // 67584 -> 2 CTAs/SM

// scan segmentation
#define NSEG 32
#define TSEG 128                 // 4096 / 32

// ---------------- scratch (__device__ globals; no allocations) ----------------
__device__ uint4  xp_g[(size_t)1024 * 64 * 32];      // x frag-packed: [band][k16][lane]
__device__ __half w1f16_g[(size_t)12 * DSZ * DIN];   // [mat*4+s][n=d][k]
__device__ __half w2f16_g[(size_t)4 * DSZ * DSZ];    // [s][n=e][k]
__device__ uint4  g1p_g[(size_t)4 * 1024 * 16 * 32]; // g1 frag-packed: [s][band][k16][lane]
__device__ __half dre_g[(size_t)4 * MTOT * DSZ];
__device__ __half dim_g[(size_t)4 * MTOT * DSZ];
__device__ float  omg_g[(size_t)4 * MTOT * DSZ];
__device__ float2 Aseg_g[512 * 256];
__device__ float2 Hseg_g[512 * 256];

// ---------------- helpers -------------------------------------------------------
__device__ __forceinline__ uint32_t pack_h2(float a, float b) {
    union { __half2 h; uint32_t u; } p;
    p.h = __halves2half2(__float2half_rn(a), __float2half_rn(b));
    return p.u;
}
__device__ __forceinline__ uint32_t smem_u32(const void* p) {
    uint32_t a;
    asm("{ .reg .u64 t; cvta.to.shared.u64 t, %1; cvt.u32.u64 %0, t; }" : "=r"(a) : "l"(p));
    return a;
}
__device__ __forceinline__ void cpa16(uint32_t dst, const void* src) {
    asm volatile("cp.async.cg.shared.global [%0], [%1], 16;" :: "r"(dst), "l"(src));
}
__device__ __forceinline__ void cpa_commit() {
    asm volatile("cp.async.commit_group;");
}
template<int N> __device__ __forceinline__ void cpa_wait() {
    asm volatile("cp.async.wait_group %0;" :: "n"(N));
}
__device__ __forceinline__ void ldsm4(uint32_t r[4], uint32_t addr) {
    asm volatile("ldmatrix.sync.aligned.m8n8.x4.shared.b16 {%0,%1,%2,%3}, [%4];"
        : "=r"(r[0]), "=r"(r[1]), "=r"(r[2]), "=r"(r[3]) : "r"(addr));
}
__device__ __forceinline__ void mma_f16u(float c[4], uint32_t a0, uint32_t a1, uint32_t a2, uint32_t a3,
                                         const uint32_t b[2]) {
    asm volatile("mma.sync.aligned.m16n8k16.row.col.f32.f16.f16.f32 "
        "{%0,%1,%2,%3}, {%4,%5,%6,%7}, {%8,%9}, {%0,%1,%2,%3};"
        : "+f"(c[0]), "+f"(c[1]), "+f"(c[2]), "+f"(c[3])
        : "r"(a0), "r"(a1), "r"(a2), "r"(a3), "r"(b[0]), "r"(b[1]));
}

// ---------------- GEMM 1 (unchanged R13/R15): A frag-direct + ks0 prefetch ------
__global__ __launch_bounds__(256, 2) void gemm1_k(
    const float* __restrict__ bg1, const float* __restrict__ bdr, const float* __restrict__ bdi)
{
    extern __shared__ char sm[];
    uint32_t s0 = smem_u32(sm);
    const int tid = threadIdx.x;

    const int mbase = blockIdx.x * 128;
    const int nb = blockIdx.y;                 // 0..23
    const int mat = nb >> 3;
    const int s = (nb >> 1) & 3;
    const int dbase = (nb & 1) * 128;

    const int lane = tid & 31, warp = tid >> 5;
    const int wm = warp & 3, wn = warp >> 2;
    const int band0 = (mbase >> 4) + wm * 2;

    const uint4* pA0 = xp_g + ((size_t)band0 * 64) * 32 + lane;
    const uint4* pA1 = xp_g + ((size_t)(band0 + 1) * 64) * 32 + lane;
    const __half* gB = w1f16_g + ((size_t)(mat * 4 + s) * DSZ + dbase) * DIN;
    const uint32_t bBase = (uint32_t)(wn * 64 + (lane & 7) + ((lane & 16) >> 1)) * LDR1
                         + ((lane >> 3) & 1) * 16;

    auto issueB = [&](int st, int k0) {
        uint32_t base = s0 + st * PLB1;
#pragma unroll
        for (int it = 0; it < 8; it++) {
            int q = tid + it * 256;
            int r = q >> 4, c = q & 15;
            cpa16(base + r * LDR1 + c * 16, gB + (size_t)r * DIN + k0 + c * 8);
        }
        cpa_commit();
    };

    float acc[2][8][4];
#pragma unroll
    for (int i = 0; i < 2; i++)
#pragma unroll
        for (int j = 0; j < 8; j++)
#pragma unroll
            for (int k = 0; k < 4; k++) acc[i][j][k] = 0.f;

    constexpr int NCH = DIN / KCH1;    // 8
    issueB(0, 0);
    issueB(1, KCH1);

    uint4 a0n = pA0[0];
    uint4 a1n = pA1[0];

    int st = 0;
    for (int ch = 0; ch < NCH; ch++) {
        if (ch >= NCH - 1) cpa_wait<0>(); else cpa_wait<1>();
        __syncthreads();
        if (ch + 2 < NCH) {
            int st2 = st + 2; if (st2 >= 3) st2 -= 3;
            issueB(st2, (ch + 2) * KCH1);
        }
        const uint4 a0c = a0n, a1c = a1n;
        if (ch + 1 < NCH) {
            a0n = pA0[(size_t)(ch + 1) * 8 * 32];
            a1n = pA1[(size_t)(ch + 1) * 8 * 32];
        }
        const uint32_t sb = s0 + st * PLB1;
#pragma unroll
        for (int ks = 0; ks < 8; ks++) {
            const int k16 = ch * 8 + ks;
            uint4 a0 = (ks == 0) ? a0c : pA0[(size_t)k16 * 32];
            uint4 a1 = (ks == 0) ? a1c : pA1[(size_t)k16 * 32];
            uint32_t bb[4][4];
#pragma unroll
            for (int nf4 = 0; nf4 < 4; nf4++)
                ldsm4(bb[nf4], sb + bBase + nf4 * (16 * LDR1) + ks * 32);
#pragma unroll
            for (int nf = 0; nf < 8; nf++) {
                const uint32_t* bp = &bb[nf >> 1][(nf & 1) * 2];
                mma_f16u(acc[0][nf], a0.x, a0.y, a0.z, a0.w, bp);
                mma_f16u(acc[1][nf], a1.x, a1.y, a1.z, a1.w, bp);
            }
        }
        if (++st >= 3) st = 0;
    }

    const int c0 = wn * 64 + (lane & 3) * 2;
    const float* bias = (mat == 0 ? bg1 : (mat == 1 ? bdr : bdi)) + s * DSZ + dbase;

    if (mat == 0) {
        uint4* gp = g1p_g + ((size_t)s * 1024 * 16) * 32;
#pragma unroll
        for (int mi = 0; mi < 2; mi++) {
            const int band = band0 + mi;
#pragma unroll
            for (int p = 0; p < 4; p++) {
                const int nf = 2 * p;
                const int col = c0 + nf * 8;
                float b0 = bias[col],      b1 = bias[col + 1];
                float b2 = bias[col + 8],  b3 = bias[col + 9];
                uint4 w;
                w.x = pack_h2(fmaxf(acc[mi][nf][0] + b0, 0.f),
                              fmaxf(acc[mi][nf][1] + b1, 0.f));
                w.y = pack_h2(fmaxf(acc[mi][nf][2] + b0, 0.f),
                              fmaxf(acc[mi][nf][3] + b1, 0.f));
                w.z = pack_h2(fmaxf(acc[mi][nf + 1][0] + b2, 0.f),
                              fmaxf(acc[mi][nf + 1][1] + b3, 0.f));
                w.w = pack_h2(fmaxf(acc[mi][nf + 1][2] + b2, 0.f),
                              fmaxf(acc[mi][nf + 1][3] + b3, 0.f));
                const int k16 = (dbase + wn * 64 + nf * 8) >> 4;
                gp[((size_t)band * 16 + k16) * 32 + lane] = w;
            }
        }
    } else {
        const int r0 = mbase + wm * 32 + (lane >> 2);
        __half* op = (mat == 1 ? dre_g : dim_g) + (size_t)s * MTOT * DSZ;
#pragma unroll
        for (int mi = 0; mi < 2; mi++)
#pragma unroll
            for (int nf = 0; nf < 8; nf++) {
                int col = c0 + nf * 8;
                float b0 = bias[col], b1 = bias[col + 1];
#pragma unroll
                for (int hh = 0; hh < 2; hh++) {
                    int r = r0 + mi * 16 + hh * 8;
                    union { __half2 h; uint32_t u; } pk;
                    pk.u = pack_h2(acc[mi][nf][hh * 2 + 0] + b0,
                                   acc[mi][nf][hh * 2 + 1] + b1);
                    *(__half2*)(op + (size_t)r * DSZ + dbase + col) = pk.h;
                }
            }
    }
}

// ---------------- GEMM 2: split-prologue B, reg-pipelined A, fast epilogue ------
__global__ __launch_bounds__(256, 2) void gemm2_k(const float* __restrict__ bg2)
{
    extern __shared__ char sm[];
    uint32_t s0 = smem_u32(sm);
    const int tid = threadIdx.x;

    const int mgrp = blockIdx.x;               // 0..31 -> 4 m-tiles each
    const int s = blockIdx.y >> 1;
    const int dbase = (blockIdx.y & 1) * 128;

    const int lane = tid & 31, warp = tid >> 5;
    const int wm = warp & 3, wn = warp >> 2;

    const __half* gB = w2f16_g + ((size_t)s * DSZ + dbase) * DSZ;

    // split B load: group A = k-halfs [0,128) (c 0..15), group B = [128,256)
#pragma unroll
    for (int it = 0; it < 8; it++) {
        int q = tid + it * 256;
        int r = q >> 4, c = q & 15;
        cpa16(s0 + r * LDR2 + c * 16, gB + (size_t)r * DSZ + c * 8);
    }
    cpa_commit();
#pragma unroll
    for (int it = 0; it < 8; it++) {
        int q = tid + it * 256;
        int r = q >> 4, c = (q & 15) + 16;
        cpa16(s0 + r * LDR2 + c * 16, gB + (size_t)r * DSZ + c * 8);
    }
    cpa_commit();

    const uint32_t bBase = (uint32_t)(wn * 64 + (lane & 7) + ((lane & 16) >> 1)) * LDR2
                         + ((lane >> 3) & 1) * 16;
    const int c0 = wn * 64 + (lane & 3) * 2;
    const float* bias = bg2 + s * DSZ + dbase;
    float* opb = omg_g + (size_t)s * MTOT * DSZ;

    cpa_wait<1>();          // first k-half resident
    __syncthreads();

    for (int mt = 0; mt < 4; mt++) {
        const int mbase = (mgrp * 4 + mt) * 128;
        const int band0 = (mbase >> 4) + wm * 2;
        const uint4* pA0 = g1p_g + ((size_t)(s * 1024 + band0) * 16) * 32 + lane;
        const uint4* pA1 = g1p_g + ((size_t)(s * 1024 + band0 + 1) * 16) * 32 + lane;

        float acc[2][8][4];
#pragma unroll
        for (int i = 0; i < 2; i++)
#pragma unroll
            for (int j = 0; j < 8; j++)
#pragma unroll
                for (int k = 0; k < 4; k++) acc[i][j][k] = 0.f;

        uint4 f0a = pA0[0],  f0b = pA1[0];
        uint4 f1a = pA0[32], f1b = pA1[32];

#pragma unroll
        for (int k16 = 0; k16 < 16; k16++) {
            if (mt == 0 && k16 == 8) {     // second k-half needed from here
                cpa_wait<0>();
                __syncthreads();
            }
            const uint4 a0 = f0a, a1 = f0b;
            f0a = f1a; f0b = f1b;
            if (k16 + 2 < 16) {
                f1a = pA0[(size_t)(k16 + 2) * 32];
                f1b = pA1[(size_t)(k16 + 2) * 32];
            }
            uint32_t bb[4][4];
#pragma unroll
            for (int nf4 = 0; nf4 < 4; nf4++)
                ldsm4(bb[nf4], s0 + bBase + nf4 * (16 * LDR2) + k16 * 32);
#pragma unroll
            for (int nf = 0; nf < 8; nf++) {
                const uint32_t* bp = &bb[nf >> 1][(nf & 1) * 2];
                mma_f16u(acc[0][nf], a0.x, a0.y, a0.z, a0.w, bp);
                mma_f16u(acc[1][nf], a1.x, a1.y, a1.z, a1.w, bp);
            }
        }

        const int r0 = mbase + wm * 32 + (lane >> 2);
#pragma unroll
        for (int mi = 0; mi < 2; mi++)
#pragma unroll
            for (int nf = 0; nf < 8; nf++) {
                int col = c0 + nf * 8;
                float b0 = bias[col], b1 = bias[col + 1];
#pragma unroll
                for (int hh = 0; hh < 2; hh++) {
                    int r = r0 + mi * 16 + hh * 8;
                    float2 v;
                    v.x = __fdividef(1.0f, 1.0f + __expf(acc[mi][nf][hh * 2 + 0] + b0));
                    v.y = __fdividef(1.0f, 1.0f + __expf(acc[mi][nf][hh * 2 + 1] + b1));
                    *(float2*)(opb + (size_t)r * DSZ + dbase + col) = v;
                }
            }
    }
}

// ---------------- merged conversion kernel --------------------------------------
// blocks [0, 8192): x -> fragment-packed fp16
// blocks [8192, 12288): W1/W2 transpose+convert
__global__ __launch_bounds__(256) void conv_all_k(
    const float* __restrict__ x,
    const float* __restrict__ Wg1, const float* __restrict__ Wdr,
    const float* __restrict__ Wdi, const float* __restrict__ Wg2)
{
    if (blockIdx.x < 8192) {
        const size_t idx = (size_t)blockIdx.x * 256 + threadIdx.x;
        const int lane = idx & 31;
        const int k16  = ((int)(idx >> 5)) & 63;
        const int band = (int)(idx >> 11);
        const int g = lane >> 2, t = lane & 3;
        const size_t r0 = (size_t)(band * 16 + g) * DIN;
        const size_t r8 = r0 + 8 * DIN;
        const int col = k16 * 16 + 2 * t;
        float2 v00 = *(const float2*)(x + r0 + col);
        float2 v10 = *(const float2*)(x + r8 + col);
        float2 v01 = *(const float2*)(x + r0 + col + 8);
        float2 v11 = *(const float2*)(x + r8 + col + 8);
        uint4 w;
        w.x = pack_h2(v00.x, v00.y);
        w.y = pack_h2(v10.x, v10.y);
        w.z = pack_h2(v01.x, v01.y);
        w.w = pack_h2(v11.x, v11.y);
        xp_g[idx] = w;
    } else {
        __shared__ float t[32][33];
        const int bid = blockIdx.x - 8192;     // 0..4095
        const int z = bid >> 8;                // 0..15
        const int rem = bid & 255;
        const int xb = rem & 31, yb = rem >> 5;
        const int kdim = (z < 12) ? DIN : DSZ;
        if (xb * 32 >= kdim) return;
        const float* base = (z < 4 ? Wg1 : (z < 8 ? Wdr : (z < 12 ? Wdi : Wg2)));
        const float* sp = base + (size_t)(z & 3) * kdim * DSZ;
        const int tx = threadIdx.x & 31, ty = threadIdx.x >> 5;
        const int k0 = xb * 32, d0 = yb * 32;
#pragma unroll
        for (int i = 0; i < 4; i++)
            t[ty + i * 8][tx] = sp[(size_t)(k0 + ty + i * 8) * DSZ + d0 + tx];
        __syncthreads();
        __half* oh = (z < 12) ? (w1f16_g + (size_t)z * DSZ * DIN)
                              : (w2f16_g + (size_t)(z - 12) * DSZ * DSZ);
#pragma unroll
        for (int i = 0; i < 4; i++) {
            int n = d0 + ty + i * 8, k = k0 + tx;
            oh[(size_t)n * kdim + k] = __float2half_rn(t[tx][ty + i * 8]);
        }
    }
}

// ---------------- segmented scan (2 phases, 32 segments) ------------------------
struct ScanConsts { float abr[4], abi[4], bsc[4]; };

__global__ __launch_bounds__(256) void scan_p1(ScanConsts c) {
    const int idx = blockIdx.x;                // b*128 + s*32 + seg
    const int seg = idx & (NSEG - 1), s = (idx >> 5) & 3, b = idx >> 7;
    const int d = threadIdx.x;
    const float abr = c.abr[s], abi = c.abi[s], bs = c.bsc[s];
    const size_t base = ((size_t)s * MTOT + (size_t)b * 4096 + seg * TSEG) * DSZ + d;
    float Ar = 1.f, Ai = 0.f, Hr = 0.f, Hi = 0.f;
#pragma unroll 4
    for (int t = 0; t < TSEG; t++) {
        size_t off = base + (size_t)t * DSZ;
        float w  = omg_g[off];
        float xr = __half2float(dre_g[off]);
        float xi = __half2float(dim_g[off]);
        float ar = w * abr, ai = w * abi, wb = w * bs;
        float br = wb * xr, bi = wb * xi;
        float nHr = fmaf(ar, Hr, fmaf(-ai, Hi, br));
        float nHi = fmaf(ar, Hi, fmaf( ai, Hr, bi));
        float nAr = fmaf(ar, Ar, -ai * Ai);
        float nAi = fmaf(ar, Ai,  ai * Ar);
        Hr = nHr; Hi = nHi; Ar = nAr; Ai = nAi;
    }
    Aseg_g[idx * 256 + d] = make_float2(Ar, Ai);
    Hseg_g[idx * 256 + d] = make_float2(Hr, Hi);
}

__global__ __launch_bounds__(256) void scan_p3(float* __restrict__ out, ScanConsts c) {
    const int idx = blockIdx.x;
    const int seg = idx & (NSEG - 1), s = (idx >> 5) & 3, b = idx >> 7;
    const int d = threadIdx.x;
    const float abr = c.abr[s], abi = c.abi[s], bs = c.bsc[s];
    const size_t base = ((size_t)s * MTOT + (size_t)b * 4096 + seg * TSEG) * DSZ + d;

    float hr = 0.f, hi = 0.f;
    const int rowbase = idx - seg;
    for (int g = 0; g < seg; g++) {
        float2 A = Aseg_g[(rowbase + g) * 256 + d];
        float2 H = Hseg_g[(rowbase + g) * 256 + d];
        float nhr = fmaf(A.x, hr, fmaf(-A.y, hi, H.x));
        float nhi = fmaf(A.x, hi, fmaf( A.y, hr, H.y));
        hr = nhr; hi = nhi;
    }

    float* op = out + ((size_t)b * 4096 + seg * TSEG) * 2048 + (size_t)s * 512 + d;
#pragma unroll 4
    for (int t = 0; t < TSEG; t++) {
        size_t off = base + (size_t)t * DSZ;
        float w  = omg_g[off];
        float xr = __half2float(dre_g[off]);
        float xi = __half2float(dim_g[off]);
        float ar = w * abr, ai = w * abi, wb = w * bs;
        float br = wb * xr, bi = wb * xi;
        float nhr = fmaf(ar, hr, fmaf(-ai, hi, br));
        float nhi = fmaf(ar, hi, fmaf( ai, hr, bi));
        hr = nhr; hi = nhi;
        op[(size_t)t * 2048]       = hr;
        op[(size_t)t * 2048 + 256] = hi;
    }
}

// ---------------- host ----------------------------------------------------------
extern "C" void kernel_launch(void* const* d_in, const int* in_sizes, int n_in,
                              void* d_out, int out_size)
{
    const float* x   = (const float*)d_in[0];
    const float* Wg1 = (const float*)d_in[1];
    const float* bg1 = (const float*)d_in[2];
    const float* Wg2 = (const float*)d_in[3];
    const float* bg2 = (const float*)d_in[4];
    const float* Wdr = (const float*)d_in[5];
    const float* bdr = (const float*)d_in[6];
    const float* Wdi = (const float*)d_in[7];
    const float* bdi = (const float*)d_in[8];
    float* out = (float*)d_out;

    cudaFuncSetAttribute(gemm1_k, cudaFuncAttributeMaxDynamicSharedMemorySize, SMEM1);
    cudaFuncSetAttribute(gemm2_k, cudaFuncAttributeMaxDynamicSharedMemorySize, SMEM2);

    conv_all_k<<<12288, 256>>>(x, Wg1, Wdr, Wdi, Wg2);

    gemm1_k<<<dim3(MTOT / 128, 24), 256, SMEM1>>>(bg1, bdr, bdi);
    gemm2_k<<<dim3(32, 8), 256, SMEM2>>>(bg2);

    ScanConsts c;
    const double r [4] = {1.0, 0.999, 0.9495, 0.9};
    const double th[4] = {0.0, 0.01,  0.505,  1.0};
    for (int s = 0; s < 4; s++) {
        c.abr[s] = (float)(r[s] * cos(th[s]));
        c.abi[s] = (float)(r[s] * sin(th[s]));
        c.bsc[s] = (float)((r[s] >= 1.0) ? (1.0 / 16.0) : (1.0 - r[s]));
    }
    scan_p1<<<512, 256>>>(c);
    scan_p3<<<512, 256>>>(out, c);
}

// round 17
// speedup vs baseline: 1.0956x; 1.0194x over previous
#include <cuda_runtime.h>
#include <cuda_fp16.h>
#include <stdint.h>
#include <math.h>

#define MTOT 16384
#define DIN  1024
#define DSZ  256

// gemm1: KCH=128 halfs (256B/row), 3-stage
#define KCH1  128
#define LDR1  272
#define PLB1  (128 * LDR1)       // 34816
#define NST1  3
#define SMEM1 (NST1 * PLB1)      // 104448 -> 2 CTAs/SM
// gemm2: whole-K B resident (512B/row)
#define LDR2  528
#define SMEM2 (128 * LDR2)       // 67584 -> 2 CTAs/SM

// scan segmentation
#define NSEG 32
#define TSEG 128                 // 4096 / 32

// ---------------- scratch (__device__ globals; no allocations) ----------------
__device__ uint4  xp_g[(size_t)1024 * 64 * 32];      // x frag-packed: [band][k16][lane]
__device__ __half w1f16_g[(size_t)12 * DSZ * DIN];   // [mat*4+s][n=d][k]
__device__ __half w2f16_g[(size_t)4 * DSZ * DSZ];    // [s][n=e][k]
__device__ uint4  g1p_g[(size_t)4 * 1024 * 16 * 32]; // g1 frag-packed: [s][band][k16][lane]
__device__ __half dre_g[(size_t)4 * MTOT * DSZ];
__device__ __half dim_g[(size_t)4 * MTOT * DSZ];
__device__ float  omg_g[(size_t)4 * MTOT * DSZ];
__device__ float2 Aseg_g[512 * 256];
__device__ float2 Hseg_g[512 * 256];

// ---------------- helpers -------------------------------------------------------
__device__ __forceinline__ uint32_t pack_h2(float a, float b) {
    union { __half2 h; uint32_t u; } p;
    p.h = __halves2half2(__float2half_rn(a), __float2half_rn(b));
    return p.u;
}
__device__ __forceinline__ uint32_t smem_u32(const void* p) {
    uint32_t a;
    asm("{ .reg .u64 t; cvta.to.shared.u64 t, %1; cvt.u32.u64 %0, t; }" : "=r"(a) : "l"(p));
    return a;
}
__device__ __forceinline__ void cpa16(uint32_t dst, const void* src) {
    asm volatile("cp.async.cg.shared.global [%0], [%1], 16;" :: "r"(dst), "l"(src));
}
__device__ __forceinline__ void cpa_commit() {
    asm volatile("cp.async.commit_group;");
}
template<int N> __device__ __forceinline__ void cpa_wait() {
    asm volatile("cp.async.wait_group %0;" :: "n"(N));
}
__device__ __forceinline__ void ldsm4(uint32_t r[4], uint32_t addr) {
    asm volatile("ldmatrix.sync.aligned.m8n8.x4.shared.b16 {%0,%1,%2,%3}, [%4];"
        : "=r"(r[0]), "=r"(r[1]), "=r"(r[2]), "=r"(r[3]) : "r"(addr));
}
__device__ __forceinline__ void mma_f16u(float c[4], uint32_t a0, uint32_t a1, uint32_t a2, uint32_t a3,
                                         const uint32_t b[2]) {
    asm volatile("mma.sync.aligned.m16n8k16.row.col.f32.f16.f16.f32 "
        "{%0,%1,%2,%3}, {%4,%5,%6,%7}, {%8,%9}, {%0,%1,%2,%3};"
        : "+f"(c[0]), "+f"(c[1]), "+f"(c[2]), "+f"(c[3])
        : "r"(a0), "r"(a1), "r"(a2), "r"(a3), "r"(b[0]), "r"(b[1]));
}

// ---------------- GEMM 1 (frozen): A frag-direct + ks0 prefetch -----------------
__global__ __launch_bounds__(256, 2) void gemm1_k(
    const float* __restrict__ bg1, const float* __restrict__ bdr, const float* __restrict__ bdi)
{
    extern __shared__ char sm[];
    uint32_t s0 = smem_u32(sm);
    const int tid = threadIdx.x;

    const int mbase = blockIdx.x * 128;
    const int nb = blockIdx.y;                 // 0..23
    const int mat = nb >> 3;
    const int s = (nb >> 1) & 3;
    const int dbase = (nb & 1) * 128;

    const int lane = tid & 31, warp = tid >> 5;
    const int wm = warp & 3, wn = warp >> 2;
    const int band0 = (mbase >> 4) + wm * 2;

    const uint4* pA0 = xp_g + ((size_t)band0 * 64) * 32 + lane;
    const uint4* pA1 = xp_g + ((size_t)(band0 + 1) * 64) * 32 + lane;
    const __half* gB = w1f16_g + ((size_t)(mat * 4 + s) * DSZ + dbase) * DIN;
    const uint32_t bBase = (uint32_t)(wn * 64 + (lane & 7) + ((lane & 16) >> 1)) * LDR1
                         + ((lane >> 3) & 1) * 16;

    auto issueB = [&](int st, int k0) {
        uint32_t base = s0 + st * PLB1;
#pragma unroll
        for (int it = 0; it < 8; it++) {
            int q = tid + it * 256;
            int r = q >> 4, c = q & 15;
            cpa16(base + r * LDR1 + c * 16, gB + (size_t)r * DIN + k0 + c * 8);
        }
        cpa_commit();
    };

    float acc[2][8][4];
#pragma unroll
    for (int i = 0; i < 2; i++)
#pragma unroll
        for (int j = 0; j < 8; j++)
#pragma unroll
            for (int k = 0; k < 4; k++) acc[i][j][k] = 0.f;

    constexpr int NCH = DIN / KCH1;    // 8
    issueB(0, 0);
    issueB(1, KCH1);

    uint4 a0n = pA0[0];
    uint4 a1n = pA1[0];

    int st = 0;
    for (int ch = 0; ch < NCH; ch++) {
        if (ch >= NCH - 1) cpa_wait<0>(); else cpa_wait<1>();
        __syncthreads();
        if (ch + 2 < NCH) {
            int st2 = st + 2; if (st2 >= 3) st2 -= 3;
            issueB(st2, (ch + 2) * KCH1);
        }
        const uint4 a0c = a0n, a1c = a1n;
        if (ch + 1 < NCH) {
            a0n = pA0[(size_t)(ch + 1) * 8 * 32];
            a1n = pA1[(size_t)(ch + 1) * 8 * 32];
        }
        const uint32_t sb = s0 + st * PLB1;
#pragma unroll
        for (int ks = 0; ks < 8; ks++) {
            const int k16 = ch * 8 + ks;
            uint4 a0 = (ks == 0) ? a0c : pA0[(size_t)k16 * 32];
            uint4 a1 = (ks == 0) ? a1c : pA1[(size_t)k16 * 32];
            uint32_t bb[4][4];
#pragma unroll
            for (int nf4 = 0; nf4 < 4; nf4++)
                ldsm4(bb[nf4], sb + bBase + nf4 * (16 * LDR1) + ks * 32);
#pragma unroll
            for (int nf = 0; nf < 8; nf++) {
                const uint32_t* bp = &bb[nf >> 1][(nf & 1) * 2];
                mma_f16u(acc[0][nf], a0.x, a0.y, a0.z, a0.w, bp);
                mma_f16u(acc[1][nf], a1.x, a1.y, a1.z, a1.w, bp);
            }
        }
        if (++st >= 3) st = 0;
    }

    const int c0 = wn * 64 + (lane & 3) * 2;
    const float* bias = (mat == 0 ? bg1 : (mat == 1 ? bdr : bdi)) + s * DSZ + dbase;

    if (mat == 0) {
        uint4* gp = g1p_g + ((size_t)s * 1024 * 16) * 32;
#pragma unroll
        for (int mi = 0; mi < 2; mi++) {
            const int band = band0 + mi;
#pragma unroll
            for (int p = 0; p < 4; p++) {
                const int nf = 2 * p;
                const int col = c0 + nf * 8;
                float b0 = bias[col],      b1 = bias[col + 1];
                float b2 = bias[col + 8],  b3 = bias[col + 9];
                uint4 w;
                w.x = pack_h2(fmaxf(acc[mi][nf][0] + b0, 0.f),
                              fmaxf(acc[mi][nf][1] + b1, 0.f));
                w.y = pack_h2(fmaxf(acc[mi][nf][2] + b0, 0.f),
                              fmaxf(acc[mi][nf][3] + b1, 0.f));
                w.z = pack_h2(fmaxf(acc[mi][nf + 1][0] + b2, 0.f),
                              fmaxf(acc[mi][nf + 1][1] + b3, 0.f));
                w.w = pack_h2(fmaxf(acc[mi][nf + 1][2] + b2, 0.f),
                              fmaxf(acc[mi][nf + 1][3] + b3, 0.f));
                const int k16 = (dbase + wn * 64 + nf * 8) >> 4;
                gp[((size_t)band * 16 + k16) * 32 + lane] = w;
            }
        }
    } else {
        const int r0 = mbase + wm * 32 + (lane >> 2);
        __half* op = (mat == 1 ? dre_g : dim_g) + (size_t)s * MTOT * DSZ;
#pragma unroll
        for (int mi = 0; mi < 2; mi++)
#pragma unroll
            for (int nf = 0; nf < 8; nf++) {
                int col = c0 + nf * 8;
                float b0 = bias[col], b1 = bias[col + 1];
#pragma unroll
                for (int hh = 0; hh < 2; hh++) {
                    int r = r0 + mi * 16 + hh * 8;
                    union { __half2 h; uint32_t u; } pk;
                    pk.u = pack_h2(acc[mi][nf][hh * 2 + 0] + b0,
                                   acc[mi][nf][hh * 2 + 1] + b1);
                    *(__half2*)(op + (size_t)r * DSZ + dbase + col) = pk.h;
                }
            }
    }
}

// ---------------- GEMM 2 (frozen R16): split-prologue, reg-pipelined, fast epi --
__global__ __launch_bounds__(256, 2) void gemm2_k(const float* __restrict__ bg2)
{
    extern __shared__ char sm[];
    uint32_t s0 = smem_u32(sm);
    const int tid = threadIdx.x;

    const int mgrp = blockIdx.x;               // 0..31 -> 4 m-tiles each
    const int s = blockIdx.y >> 1;
    const int dbase = (blockIdx.y & 1) * 128;

    const int lane = tid & 31, warp = tid >> 5;
    const int wm = warp & 3, wn = warp >> 2;

    const __half* gB = w2f16_g + ((size_t)s * DSZ + dbase) * DSZ;

#pragma unroll
    for (int it = 0; it < 8; it++) {
        int q = tid + it * 256;
        int r = q >> 4, c = q & 15;
        cpa16(s0 + r * LDR2 + c * 16, gB + (size_t)r * DSZ + c * 8);
    }
    cpa_commit();
#pragma unroll
    for (int it = 0; it < 8; it++) {
        int q = tid + it * 256;
        int r = q >> 4, c = (q & 15) + 16;
        cpa16(s0 + r * LDR2 + c * 16, gB + (size_t)r * DSZ + c * 8);
    }
    cpa_commit();

    const uint32_t bBase = (uint32_t)(wn * 64 + (lane & 7) + ((lane & 16) >> 1)) * LDR2
                         + ((lane >> 3) & 1) * 16;
    const int c0 = wn * 64 + (lane & 3) * 2;
    const float* bias = bg2 + s * DSZ + dbase;
    float* opb = omg_g + (size_t)s * MTOT * DSZ;

    cpa_wait<1>();
    __syncthreads();

    for (int mt = 0; mt < 4; mt++) {
        const int mbase = (mgrp * 4 + mt) * 128;
        const int band0 = (mbase >> 4) + wm * 2;
        const uint4* pA0 = g1p_g + ((size_t)(s * 1024 + band0) * 16) * 32 + lane;
        const uint4* pA1 = g1p_g + ((size_t)(s * 1024 + band0 + 1) * 16) * 32 + lane;

        float acc[2][8][4];
#pragma unroll
        for (int i = 0; i < 2; i++)
#pragma unroll
            for (int j = 0; j < 8; j++)
#pragma unroll
                for (int k = 0; k < 4; k++) acc[i][j][k] = 0.f;

        uint4 f0a = pA0[0],  f0b = pA1[0];
        uint4 f1a = pA0[32], f1b = pA1[32];

#pragma unroll
        for (int k16 = 0; k16 < 16; k16++) {
            if (mt == 0 && k16 == 8) {
                cpa_wait<0>();
                __syncthreads();
            }
            const uint4 a0 = f0a, a1 = f0b;
            f0a = f1a; f0b = f1b;
            if (k16 + 2 < 16) {
                f1a = pA0[(size_t)(k16 + 2) * 32];
                f1b = pA1[(size_t)(k16 + 2) * 32];
            }
            uint32_t bb[4][4];
#pragma unroll
            for (int nf4 = 0; nf4 < 4; nf4++)
                ldsm4(bb[nf4], s0 + bBase + nf4 * (16 * LDR2) + k16 * 32);
#pragma unroll
            for (int nf = 0; nf < 8; nf++) {
                const uint32_t* bp = &bb[nf >> 1][(nf & 1) * 2];
                mma_f16u(acc[0][nf], a0.x, a0.y, a0.z, a0.w, bp);
                mma_f16u(acc[1][nf], a1.x, a1.y, a1.z, a1.w, bp);
            }
        }

        const int r0 = mbase + wm * 32 + (lane >> 2);
#pragma unroll
        for (int mi = 0; mi < 2; mi++)
#pragma unroll
            for (int nf = 0; nf < 8; nf++) {
                int col = c0 + nf * 8;
                float b0 = bias[col], b1 = bias[col + 1];
#pragma unroll
                for (int hh = 0; hh < 2; hh++) {
                    int r = r0 + mi * 16 + hh * 8;
                    float2 v;
                    v.x = __fdividef(1.0f, 1.0f + __expf(acc[mi][nf][hh * 2 + 0] + b0));
                    v.y = __fdividef(1.0f, 1.0f + __expf(acc[mi][nf][hh * 2 + 1] + b1));
                    *(float2*)(opb + (size_t)r * DSZ + dbase + col) = v;
                }
            }
    }
}

// ---------------- merged conversion kernel --------------------------------------
__global__ __launch_bounds__(256) void conv_all_k(
    const float* __restrict__ x,
    const float* __restrict__ Wg1, const float* __restrict__ Wdr,
    const float* __restrict__ Wdi, const float* __restrict__ Wg2)
{
    if (blockIdx.x < 8192) {
        const size_t idx = (size_t)blockIdx.x * 256 + threadIdx.x;
        const int lane = idx & 31;
        const int k16  = ((int)(idx >> 5)) & 63;
        const int band = (int)(idx >> 11);
        const int g = lane >> 2, t = lane & 3;
        const size_t r0 = (size_t)(band * 16 + g) * DIN;
        const size_t r8 = r0 + 8 * DIN;
        const int col = k16 * 16 + 2 * t;
        float2 v00 = *(const float2*)(x + r0 + col);
        float2 v10 = *(const float2*)(x + r8 + col);
        float2 v01 = *(const float2*)(x + r0 + col + 8);
        float2 v11 = *(const float2*)(x + r8 + col + 8);
        uint4 w;
        w.x = pack_h2(v00.x, v00.y);
        w.y = pack_h2(v10.x, v10.y);
        w.z = pack_h2(v01.x, v01.y);
        w.w = pack_h2(v11.x, v11.y);
        xp_g[idx] = w;
    } else {
        __shared__ float t[32][33];
        const int bid = blockIdx.x - 8192;
        const int z = bid >> 8;
        const int rem = bid & 255;
        const int xb = rem & 31, yb = rem >> 5;
        const int kdim = (z < 12) ? DIN : DSZ;
        if (xb * 32 >= kdim) return;
        const float* base = (z < 4 ? Wg1 : (z < 8 ? Wdr : (z < 12 ? Wdi : Wg2)));
        const float* sp = base + (size_t)(z & 3) * kdim * DSZ;
        const int tx = threadIdx.x & 31, ty = threadIdx.x >> 5;
        const int k0 = xb * 32, d0 = yb * 32;
#pragma unroll
        for (int i = 0; i < 4; i++)
            t[ty + i * 8][tx] = sp[(size_t)(k0 + ty + i * 8) * DSZ + d0 + tx];
        __syncthreads();
        __half* oh = (z < 12) ? (w1f16_g + (size_t)z * DSZ * DIN)
                              : (w2f16_g + (size_t)(z - 12) * DSZ * DSZ);
#pragma unroll
        for (int i = 0; i < 4; i++) {
            int n = d0 + ty + i * 8, k = k0 + tx;
            oh[(size_t)n * kdim + k] = __float2half_rn(t[tx][ty + i * 8]);
        }
    }
}

// ---------------- segmented scan (2 phases, deeper unroll) ----------------------
struct ScanConsts { float abr[4], abi[4], bsc[4]; };

__global__ __launch_bounds__(256) void scan_p1(ScanConsts c) {
    const int idx = blockIdx.x;                // b*128 + s*32 + seg
    const int seg = idx & (NSEG - 1), s = (idx >> 5) & 3, b = idx >> 7;
    const int d = threadIdx.x;
    const float abr = c.abr[s], abi = c.abi[s], bs = c.bsc[s];
    const size_t base = ((size_t)s * MTOT + (size_t)b * 4096 + seg * TSEG) * DSZ + d;
    float Ar = 1.f, Ai = 0.f, Hr = 0.f, Hi = 0.f;
#pragma unroll 8
    for (int t = 0; t < TSEG; t++) {
        size_t off = base + (size_t)t * DSZ;
        float w  = omg_g[off];
        float xr = __half2float(dre_g[off]);
        float xi = __half2float(dim_g[off]);
        float ar = w * abr, ai = w * abi, wb = w * bs;
        float br = wb * xr, bi = wb * xi;
        float nHr = fmaf(ar, Hr, fmaf(-ai, Hi, br));
        float nHi = fmaf(ar, Hi, fmaf( ai, Hr, bi));
        float nAr = fmaf(ar, Ar, -ai * Ai);
        float nAi = fmaf(ar, Ai,  ai * Ar);
        Hr = nHr; Hi = nHi; Ar = nAr; Ai = nAi;
    }
    Aseg_g[idx * 256 + d] = make_float2(Ar, Ai);
    Hseg_g[idx * 256 + d] = make_float2(Hr, Hi);
}

__global__ __launch_bounds__(256) void scan_p3(float* __restrict__ out, ScanConsts c) {
    const int idx = blockIdx.x;
    const int seg = idx & (NSEG - 1), s = (idx >> 5) & 3, b = idx >> 7;
    const int d = threadIdx.x;
    const float abr = c.abr[s], abi = c.abi[s], bs = c.bsc[s];
    const size_t base = ((size_t)s * MTOT + (size_t)b * 4096 + seg * TSEG) * DSZ + d;

    // batched lookback: load 4 predecessor aggregates at once, fold in order
    float hr = 0.f, hi = 0.f;
    const int rowbase = idx - seg;
    int g = 0;
    for (; g + 4 <= seg; g += 4) {
        float2 A0 = Aseg_g[(rowbase + g + 0) * 256 + d];
        float2 H0 = Hseg_g[(rowbase + g + 0) * 256 + d];
        float2 A1 = Aseg_g[(rowbase + g + 1) * 256 + d];
        float2 H1 = Hseg_g[(rowbase + g + 1) * 256 + d];
        float2 A2 = Aseg_g[(rowbase + g + 2) * 256 + d];
        float2 H2 = Hseg_g[(rowbase + g + 2) * 256 + d];
        float2 A3 = Aseg_g[(rowbase + g + 3) * 256 + d];
        float2 H3 = Hseg_g[(rowbase + g + 3) * 256 + d];
        float t0r = fmaf(A0.x, hr, fmaf(-A0.y, hi, H0.x));
        float t0i = fmaf(A0.x, hi, fmaf( A0.y, hr, H0.y));
        float t1r = fmaf(A1.x, t0r, fmaf(-A1.y, t0i, H1.x));
        float t1i = fmaf(A1.x, t0i, fmaf( A1.y, t0r, H1.y));
        float t2r = fmaf(A2.x, t1r, fmaf(-A2.y, t1i, H2.x));
        float t2i = fmaf(A2.x, t1i, fmaf( A2.y, t1r, H2.y));
        hr = fmaf(A3.x, t2r, fmaf(-A3.y, t2i, H3.x));
        hi = fmaf(A3.x, t2i, fmaf( A3.y, t2r, H3.y));
    }
    for (; g < seg; g++) {
        float2 A = Aseg_g[(rowbase + g) * 256 + d];
        float2 H = Hseg_g[(rowbase + g) * 256 + d];
        float nhr = fmaf(A.x, hr, fmaf(-A.y, hi, H.x));
        float nhi = fmaf(A.x, hi, fmaf( A.y, hr, H.y));
        hr = nhr; hi = nhi;
    }

    float* op = out + ((size_t)b * 4096 + seg * TSEG) * 2048 + (size_t)s * 512 + d;
#pragma unroll 8
    for (int t = 0; t < TSEG; t++) {
        size_t off = base + (size_t)t * DSZ;
        float w  = omg_g[off];
        float xr = __half2float(dre_g[off]);
        float xi = __half2float(dim_g[off]);
        float ar = w * abr, ai = w * abi, wb = w * bs;
        float br = wb * xr, bi = wb * xi;
        float nhr = fmaf(ar, hr, fmaf(-ai, hi, br));
        float nhi = fmaf(ar, hi, fmaf( ai, hr, bi));
        hr = nhr; hi = nhi;
        op[(size_t)t * 2048]       = hr;
        op[(size_t)t * 2048 + 256] = hi;
    }
}

// ---------------- host ----------------------------------------------------------
extern "C" void kernel_launch(void* const* d_in, const int* in_sizes, int n_in,
                              void* d_out, int out_size)
{
    const float* x   = (const float*)d_in[0];
    const float* Wg1 = (const float*)d_in[1];
    const float* bg1 = (const float*)d_in[2];
    const float* Wg2 = (const float*)d_in[3];
    const float* bg2 = (const float*)d_in[4];
    const float* Wdr = (const float*)d_in[5];
    const float* bdr = (const float*)d_in[6];
    const float* Wdi = (const float*)d_in[7];
    const float* bdi = (const float*)d_in[8];
    float* out = (float*)d_out;

    cudaFuncSetAttribute(gemm1_k, cudaFuncAttributeMaxDynamicSharedMemorySize, SMEM1);
    cudaFuncSetAttribute(gemm2_k, cudaFuncAttributeMaxDynamicSharedMemorySize, SMEM2);

    conv_all_k<<<12288, 256>>>(x, Wg1, Wdr, Wdi, Wg2);

    gemm1_k<<<dim3(MTOT / 128, 24), 256, SMEM1>>>(bg1, bdr, bdi);
    gemm2_k<<<dim3(32, 8), 256, SMEM2>>>(bg2);

    ScanConsts c;
    const double r [4] = {1.0, 0.999, 0.9495, 0.9};
    const double th[4] = {0.0, 0.01,  0.505,  1.0};
    for (int s = 0; s < 4; s++) {
        c.abr[s] = (float)(r[s] * cos(th[s]));
        c.abi[s] = (float)(r[s] * sin(th[s]));
        c.bsc[s] = (float)((r[s] >= 1.0) ? (1.0 / 16.0) : (1.0 - r[s]));
    }
    scan_p1<<<512, 256>>>(c);
    scan_p3<<<512, 256>>>(out, c);
}